// round 2
// baseline (speedup 1.0000x reference)
#include <cuda_runtime.h>
#include <math.h>

#ifndef M_PI
#define M_PI 3.14159265358979323846
#endif

#define N_TOT   8388608
#define W       882
#define NB      9510          // N_TOT / W
#define REM     788           // N_TOT - NB*W
#define MCH     64            // karplus steps per chunk
#define NFULL   148           // full chunks
#define NCH     149           // total chunks (last has 38 steps)
#define LASTS   38
#define LBQ     2048          // biquad chunk length
#define PBQ     4096          // biquad chunk count (LBQ*PBQ = N_TOT)
#define SRATE   44100.0

// ---- scratch (device globals; no allocation allowed) ----
__device__ float  g_wt[W];                 // filtered wavetable (karplus init state)
__device__ float  g_K64[MCH + 1];          // kernel of S^64 (circular conv taps)
__device__ float  g_dstate[NFULL * W];     // karplus chunk end-states (zero-init runs)
__device__ float  g_vstart[NCH * W];       // karplus chunk start-states (exact)
__device__ float  g_ks[N_TOT];             // karplus output = band-reject input
__device__ float  g_bqd[PBQ * 2];          // biquad per-chunk zero-init end states (y1,y2)
__device__ float  g_bqs[PBQ * 2];          // biquad per-chunk start states
__device__ double g_Ms[12][4];             // M^(LBQ * 2^s), s = 0..11
__device__ float  g_par[12];               // 0:d2 1:fa 2..6:bq coefs 7:inv_attack 8:inv_release 9:sustain*gain

// ============================================================
// Setup: all scalars, wavetable prefilter (serial, tiny), S^64
// kernel, band-reject coefs, M^L powers, envelope params.
// ============================================================
__global__ void setup_kernel(const float* __restrict__ wavetable,
                             const float* __restrict__ h,
                             const float* __restrict__ envp,
                             const float* __restrict__ lp2) {
    if (threadIdx.x != 0 || blockIdx.x != 0) return;

    double h0 = h[0], h1 = h[1], h2 = h[2], h3 = h[3], h4 = h[4], h5 = h[5], h6 = h[6];

    double decay = h0 / 10.0 + 0.9;
    decay = fmin(fmax(decay, 0.9), 0.999);
    double d2 = decay * 0.5;

    // ---- lowpass 1 ----
    double lpf = h1 * SRATE / 4.0; lpf = fmin(fmax(lpf, 100.0), SRATE / 2.0 - 1.0);
    double lpq = fmin(fmax(h2, 0.1), 0.999);
    double w0 = 2.0 * M_PI * lpf / SRATE, al = sin(w0) / (2.0 * lpq), cw = cos(w0);
    double a0 = 1.0 + al;
    double f1b0 = ((1.0 - cw) * 0.5) / a0, f1b1 = (1.0 - cw) / a0, f1b2 = f1b0;
    double f1a1 = (-2.0 * cw) / a0, f1a2 = (1.0 - al) / a0;

    // ---- lowpass 2 ----
    double c2 = 100.0 + (double)lp2[0] * 8000.0;
    double w02 = 2.0 * M_PI * c2 / SRATE, al2 = sin(w02) / (2.0 * 0.707), cw2 = cos(w02);
    double a02 = 1.0 + al2;
    double f2b0 = ((1.0 - cw2) * 0.5) / a02, f2b1 = (1.0 - cw2) / a02, f2b2 = f2b0;
    double f2a1 = (-2.0 * cw2) / a02, f2a2 = (1.0 - al2) / a02;

    // ---- cascade over wavetable (882 samples, serial) ----
    {
        double x1 = 0, x2 = 0, y1 = 0, y2 = 0, u1 = 0, u2 = 0, v1 = 0, v2 = 0;
        for (int i = 0; i < W; i++) {
            double xn = (double)wavetable[i];
            double yn = f1b0 * xn + f1b1 * x1 + f1b2 * x2 - f1a1 * y1 - f1a2 * y2;
            x2 = x1; x1 = xn; y2 = y1; y1 = yn;
            double zn = f2b0 * yn + f2b1 * u1 + f2b2 * u2 - f2a1 * v1 - f2a2 * v2;
            u2 = u1; u1 = yn; v2 = v1; v1 = zn;
            g_wt[i] = (float)zn;
        }
    }

    // ---- kernel of S^64:  K[j] = (d/2)^64 * C(64, j) built iteratively ----
    {
        double K[MCH + 1];
        K[0] = 1.0;
        for (int j = 1; j <= MCH; j++) K[j] = 0.0;
        for (int s = 0; s < MCH; s++) {
            for (int j = MCH; j >= 1; j--) K[j] = d2 * (K[j] + K[j - 1]);
            K[0] *= d2;
        }
        for (int j = 0; j <= MCH; j++) g_K64[j] = (float)K[j];
    }

    // ---- band-reject coefs ----
    double brf = h5 * SRATE / 4.0; brf = fmin(fmax(brf, 100.0), SRATE / 2.0 - 1.0);
    double brq = fmin(fmax(h6, 0.1), 0.999);
    double w0b = 2.0 * M_PI * brf / SRATE, alb = sin(w0b) / (2.0 * brq), cwb = cos(w0b);
    double a0b = 1.0 + alb;
    double bb0 = 1.0 / a0b, bb1 = (-2.0 * cwb) / a0b, bb2 = 1.0 / a0b;
    double ba1 = (-2.0 * cwb) / a0b, ba2 = (1.0 - alb) / a0b;

    // ---- M^(LBQ * 2^s) by repeated squaring (double) ----
    {
        double m00 = -ba1, m01 = -ba2, m10 = 1.0, m11 = 0.0;   // M
        for (int s = 0; s < 11; s++) {                          // -> M^2048
            double n00 = m00 * m00 + m01 * m10, n01 = m00 * m01 + m01 * m11;
            double n10 = m10 * m00 + m11 * m10, n11 = m10 * m01 + m11 * m11;
            m00 = n00; m01 = n01; m10 = n10; m11 = n11;
        }
        for (int s = 0; s < 12; s++) {
            g_Ms[s][0] = m00; g_Ms[s][1] = m01; g_Ms[s][2] = m10; g_Ms[s][3] = m11;
            double n00 = m00 * m00 + m01 * m10, n01 = m00 * m01 + m01 * m11;
            double n10 = m10 * m00 + m11 * m10, n11 = m10 * m01 + m11 * m11;
            m00 = n00; m01 = n01; m10 = n10; m11 = n11;
        }
    }

    // ---- envelope ----
    double nD = (double)N_TOT;
    double attack  = 1.0 + (double)envp[0] * 0.1 * nD;
    double release = 1.0 + (double)envp[2] * 0.1 * nD;
    double sustain = fmin(fmax((double)envp[1], 0.0), 1.0);

    g_par[0] = (float)d2;
    g_par[1] = (float)h3;          // feedbackamt
    g_par[2] = (float)bb0; g_par[3] = (float)bb1; g_par[4] = (float)bb2;
    g_par[5] = (float)ba1; g_par[6] = (float)ba2;
    g_par[7] = (float)(1.0 / attack);
    g_par[8] = (float)(1.0 / release);
    g_par[9] = (float)(sustain * h4);
}

// ============================================================
// Karplus pass 1: zero-init chunk runs -> end states d_c
// ============================================================
__global__ void __launch_bounds__(896) ks_pass1(const float* __restrict__ fb) {
    __shared__ float a[W];
    __shared__ float b[W];
    int c = blockIdx.x;
    int i = threadIdx.x;
    bool act = i < W;
    int im1 = (i == 0) ? (W - 1) : (i - 1);
    float d2 = g_par[0], fa = g_par[1];

    if (act) a[i] = 0.0f;
    __syncthreads();

    const float* fp = fb + (size_t)c * MCH * W + i;
    float xnext = act ? fp[0] : 0.0f;
    for (int s = 0; s < MCH; s++) {
        float x = xnext;
        if (act && s + 1 < MCH) xnext = fp[(size_t)(s + 1) * W];
        float u = act ? tanhf(fa * x) : 0.0f;
        if (act) b[i] = a[i] + u;
        __syncthreads();
        if (act) a[i] = d2 * (b[i] + b[im1]);
        __syncthreads();
    }
    if (act) g_dstate[c * W + i] = a[i];
}

// ============================================================
// Karplus combine: sequential over 148 boundaries,
// v_{c} = S^64 (circular conv, 65 taps) * v_{c-1} + d_{c-1}
// 294 threads x 3 outputs, sliding-window register reuse.
// ============================================================
__global__ void __launch_bounds__(320) ks_combine() {
    __shared__ float v[W];
    __shared__ float Ks[MCH + 1];
    int i = threadIdx.x;

    if (i <= MCH) Ks[i] = g_K64[i];
    for (int t = i; t < W; t += blockDim.x) {
        float w = g_wt[t];
        v[t] = w;
        g_vstart[t] = w;          // chunk 0 starts from wt
    }
    __syncthreads();

    const int o0 = i * 3;
    bool act = (i < 294);          // 294*3 = 882
    for (int c = 1; c < NCH; c++) {
        float acc0 = 0.f, acc1 = 0.f, acc2 = 0.f;
        if (act) {
            const float* dp = g_dstate + (size_t)(c - 1) * W + o0;
            acc0 = dp[0]; acc1 = dp[1]; acc2 = dp[2];
            float p1 = v[o0 + 1];
            float p2 = v[o0 + 2];
            int idx = o0;
            #pragma unroll
            for (int j = 0; j <= MCH; j++) {
                float x  = v[idx];
                float kj = Ks[j];
                acc0 = fmaf(kj, x,  acc0);
                acc1 = fmaf(kj, p1, acc1);
                acc2 = fmaf(kj, p2, acc2);
                p2 = p1; p1 = x;
                idx = idx ? idx - 1 : W - 1;
            }
        }
        __syncthreads();
        if (act) {
            v[o0] = acc0; v[o0 + 1] = acc1; v[o0 + 2] = acc2;
            float* vs = g_vstart + (size_t)c * W + o0;
            vs[0] = acc0; vs[1] = acc1; vs[2] = acc2;
        }
        __syncthreads();
    }
}

// ============================================================
// Karplus pass 2: replay chunks from exact start states, write
// outputs; last chunk handles the 788-sample remainder + fade.
// ============================================================
__global__ void __launch_bounds__(896) ks_pass2(const float* __restrict__ fb) {
    __shared__ float a[W];
    __shared__ float b[W];
    int c = blockIdx.x;
    int i = threadIdx.x;
    bool act = i < W;
    int im1 = (i == 0) ? (W - 1) : (i - 1);
    float d2 = g_par[0], fa = g_par[1];

    if (act) a[i] = g_vstart[(size_t)c * W + i];
    __syncthreads();

    int nsteps = (c == NCH - 1) ? LASTS : MCH;
    const float* fp = fb   + (size_t)c * MCH * W + i;
    float*       op = g_ks + (size_t)c * MCH * W + i;
    float xnext = act ? fp[0] : 0.0f;
    for (int s = 0; s < nsteps; s++) {
        float x = xnext;
        if (act && s + 1 < nsteps) xnext = fp[(size_t)(s + 1) * W];
        float u = act ? tanhf(fa * x) : 0.0f;
        if (act) b[i] = a[i] + u;
        __syncthreads();
        if (act) {
            float nv = d2 * (b[i] + b[im1]);
            a[i] = nv;
            op[(size_t)s * W] = nv;
        }
        __syncthreads();
    }

    if (c == NCH - 1) {
        // one extra smoothing (no input add), output first REM samples with fade
        if (act) b[i] = a[i];
        __syncthreads();
        if (i < REM) {
            float fin = d2 * (b[i] + b[im1]);
            int g = NB * W + i;
            if (g >= N_TOT - 256) fin *= (float)(N_TOT - 1 - g) * (1.0f / 255.0f);
            g_ks[g] = fin;
        }
    }
}

// ============================================================
// Band-reject pass A: per-chunk zero-init runs -> end states
// ============================================================
__global__ void bq_passA() {
    int c = blockIdx.x * blockDim.x + threadIdx.x;
    if (c >= PBQ) return;
    float b0 = g_par[2], b1 = g_par[3], b2 = g_par[4], a1 = g_par[5], a2 = g_par[6];
    int start = c * LBQ;
    float x1 = (start >= 1) ? g_ks[start - 1] : 0.0f;
    float x2 = (start >= 2) ? g_ks[start - 2] : 0.0f;
    float y1 = 0.0f, y2 = 0.0f;
    #pragma unroll 4
    for (int k = 0; k < LBQ; k++) {
        float xn = g_ks[start + k];
        float cn = b0 * xn + b1 * x1 + b2 * x2;
        float yn = cn - a1 * y1 - a2 * y2;
        x2 = x1; x1 = xn; y2 = y1; y1 = yn;
    }
    g_bqd[2 * c] = y1;
    g_bqd[2 * c + 1] = y2;
}

// ============================================================
// Band-reject scan: Kogge-Stone over 4096 chunk states,
// v_c += M^(L*2^s) * v_{c-2^s}
// ============================================================
__global__ void __launch_bounds__(1024) bq_scan() {
    __shared__ float2 sv[PBQ];
    int tid = threadIdx.x;
    for (int e = 0; e < 4; e++) {
        int c = tid * 4 + e;
        sv[c] = make_float2(g_bqd[2 * c], g_bqd[2 * c + 1]);
    }
    __syncthreads();
    for (int s = 0; s < 12; s++) {
        int off = 1 << s;
        float A00 = (float)g_Ms[s][0], A01 = (float)g_Ms[s][1];
        float A10 = (float)g_Ms[s][2], A11 = (float)g_Ms[s][3];
        float2 add[4];
        for (int e = 0; e < 4; e++) {
            int c = tid * 4 + e;
            if (c >= off) {
                float2 src = sv[c - off];
                add[e] = make_float2(A00 * src.x + A01 * src.y,
                                     A10 * src.x + A11 * src.y);
            } else {
                add[e] = make_float2(0.f, 0.f);
            }
        }
        __syncthreads();
        for (int e = 0; e < 4; e++) {
            int c = tid * 4 + e;
            sv[c].x += add[e].x;
            sv[c].y += add[e].y;
        }
        __syncthreads();
    }
    // exclusive: start state of chunk c = inclusive state of chunk c-1
    for (int e = 0; e < 4; e++) {
        int c = tid * 4 + e;
        if (c < PBQ - 1) {
            g_bqs[2 * (c + 1)]     = sv[c].x;
            g_bqs[2 * (c + 1) + 1] = sv[c].y;
        }
    }
    if (tid == 0) { g_bqs[0] = 0.f; g_bqs[1] = 0.f; }
}

// ============================================================
// Band-reject pass B: replay from exact states, fuse envelope
// ============================================================
__global__ void bq_passB(float* __restrict__ out) {
    int c = blockIdx.x * blockDim.x + threadIdx.x;
    if (c >= PBQ) return;
    float b0 = g_par[2], b1 = g_par[3], b2 = g_par[4], a1 = g_par[5], a2 = g_par[6];
    float ia = g_par[7], ir = g_par[8], sg = g_par[9];
    int start = c * LBQ;
    float x1 = (start >= 1) ? g_ks[start - 1] : 0.0f;
    float x2 = (start >= 2) ? g_ks[start - 2] : 0.0f;
    float y1 = g_bqs[2 * c], y2 = g_bqs[2 * c + 1];
    #pragma unroll 4
    for (int k = 0; k < LBQ; k++) {
        int n = start + k;
        float xn = g_ks[n];
        float cn = b0 * xn + b1 * x1 + b2 * x2;
        float yn = cn - a1 * y1 - a2 * y2;
        x2 = x1; x1 = xn; y2 = y1; y1 = yn;
        float fn = (float)n;
        float e1 = fminf(fn * ia, 1.0f);
        float e2 = fminf(((float)(N_TOT - 1) - fn) * ir, 1.0f);
        out[n] = yn * e1 * e2 * sg;
    }
}

// ============================================================
extern "C" void kernel_launch(void* const* d_in, const int* in_sizes, int n_in,
                              void* d_out, int out_size) {
    const float* fb  = (const float*)d_in[0];
    const float* wt  = (const float*)d_in[1];
    const float* h   = (const float*)d_in[2];
    const float* ep  = (const float*)d_in[3];
    const float* lp2 = (const float*)d_in[4];
    float* out = (float*)d_out;

    setup_kernel<<<1, 1>>>(wt, h, ep, lp2);
    ks_pass1<<<NFULL, 896>>>(fb);
    ks_combine<<<1, 320>>>();
    ks_pass2<<<NCH, 896>>>(fb);
    bq_passA<<<PBQ / 128, 128>>>();
    bq_scan<<<1, 1024>>>();
    bq_passB<<<PBQ / 128, 128>>>(out);
}

// round 3
// speedup vs baseline: 4.5850x; 4.5850x over previous
#include <cuda_runtime.h>
#include <math.h>

#ifndef M_PI
#define M_PI 3.14159265358979323846
#endif

#define N_TOT   8388608
#define W       882
#define WP      884           // padded row stride (16B-aligned rows)
#define NB      9510          // N_TOT / W
#define REM     788           // N_TOT - NB*W
#define MCH     64            // karplus steps per chunk
#define NFULL   148           // full chunks
#define NCH     149           // total chunks (last has 38 steps)
#define LASTS   38
#define J0      12            // first kept tap of K64
#define NT      41            // taps 12..52
#define LBQ     1024          // biquad chunk length
#define PBQ     8192          // biquad chunk count (LBQ*PBQ = N_TOT)
#define SRATE   44100.0

// ---- scratch (device globals; no allocation allowed) ----
__device__ float  g_wt[W];                 // filtered wavetable (karplus init state)
__device__ float  g_K64[MCH + 1];          // kernel of S^64 (circular conv taps)
__device__ float  g_dstate[NFULL * WP];    // karplus chunk end-states (zero-init runs)
__device__ float  g_vstart[NCH * WP];      // karplus chunk start-states (exact)
__device__ float  g_ks[N_TOT];             // karplus output = band-reject input
__device__ float  g_bqd[PBQ * 2];          // biquad per-chunk zero-init end states (y1,y2)
__device__ float  g_bqs[PBQ * 2];          // biquad per-chunk start states
__device__ double g_Ms[13][4];             // M^(LBQ * 2^s), s = 0..12
__device__ float  g_par[12];               // 0:d2 1:fa 2..6:bq coefs 7:inv_attack 8:inv_release 9:sustain*gain

// ============================================================
// Setup. Thread 0: scalars + wavetable prefilter (f32 serial) +
// matrix powers. Threads 32..96: K64 taps via closed-form binomial.
// ============================================================
__global__ void setup_kernel(const float* __restrict__ wavetable,
                             const float* __restrict__ h,
                             const float* __restrict__ envp,
                             const float* __restrict__ lp2) {
    int tid = threadIdx.x;

    // ---- parallel K64 taps: K[j] = C(64,j) * d2^64 ----
    if (tid >= 32 && tid < 32 + MCH + 1) {
        int j = tid - 32;
        double decay = (double)h[0] / 10.0 + 0.9;
        decay = fmin(fmax(decay, 0.9), 0.999);
        double d2 = decay * 0.5;
        int m = (j < MCH - j) ? j : (MCH - j);
        double b = 1.0;
        for (int i = 1; i <= m; i++) b = b * (double)(MCH - m + i) / (double)i;
        // d2^64 via 6 squarings
        double p = d2;
        p = p * p; p = p * p; p = p * p; p = p * p; p = p * p; p = p * p;
        g_K64[j] = (float)(b * p);
    }

    if (tid != 0) return;

    double h0 = h[0], h1 = h[1], h2 = h[2], h3 = h[3], h4 = h[4], h5 = h[5], h6 = h[6];

    double decay = h0 / 10.0 + 0.9;
    decay = fmin(fmax(decay, 0.9), 0.999);
    double d2 = decay * 0.5;

    // ---- lowpass 1 coefs ----
    double lpf = h1 * SRATE / 4.0; lpf = fmin(fmax(lpf, 100.0), SRATE / 2.0 - 1.0);
    double lpq = fmin(fmax(h2, 0.1), 0.999);
    double w0 = 2.0 * M_PI * lpf / SRATE, al = sin(w0) / (2.0 * lpq), cw = cos(w0);
    double a0 = 1.0 + al;
    float f1b0 = (float)(((1.0 - cw) * 0.5) / a0), f1b1 = (float)((1.0 - cw) / a0);
    float f1b2 = f1b0;
    float f1a1 = (float)((-2.0 * cw) / a0), f1a2 = (float)((1.0 - al) / a0);

    // ---- lowpass 2 coefs ----
    double c2 = 100.0 + (double)lp2[0] * 8000.0;
    double w02 = 2.0 * M_PI * c2 / SRATE, al2 = sin(w02) / (2.0 * 0.707), cw2 = cos(w02);
    double a02 = 1.0 + al2;
    float f2b0 = (float)(((1.0 - cw2) * 0.5) / a02), f2b1 = (float)((1.0 - cw2) / a02);
    float f2b2 = f2b0;
    float f2a1 = (float)((-2.0 * cw2) / a02), f2a2 = (float)((1.0 - al2) / a02);

    // ---- cascade over wavetable (882 samples, serial f32) ----
    {
        float x1 = 0.f, x2 = 0.f, y1 = 0.f, y2 = 0.f, u1 = 0.f, u2 = 0.f, v1 = 0.f, v2 = 0.f;
        for (int i = 0; i < W; i++) {
            float xn = wavetable[i];
            float yn = f1b0 * xn + f1b1 * x1 + f1b2 * x2 - f1a1 * y1 - f1a2 * y2;
            x2 = x1; x1 = xn; y2 = y1; y1 = yn;
            float zn = f2b0 * yn + f2b1 * u1 + f2b2 * u2 - f2a1 * v1 - f2a2 * v2;
            u2 = u1; u1 = yn; v2 = v1; v1 = zn;
            g_wt[i] = zn;
        }
    }

    // ---- band-reject coefs ----
    double brf = h5 * SRATE / 4.0; brf = fmin(fmax(brf, 100.0), SRATE / 2.0 - 1.0);
    double brq = fmin(fmax(h6, 0.1), 0.999);
    double w0b = 2.0 * M_PI * brf / SRATE, alb = sin(w0b) / (2.0 * brq), cwb = cos(w0b);
    double a0b = 1.0 + alb;
    double bb0 = 1.0 / a0b, bb1 = (-2.0 * cwb) / a0b, bb2 = 1.0 / a0b;
    double ba1 = (-2.0 * cwb) / a0b, ba2 = (1.0 - alb) / a0b;

    // ---- M^(LBQ * 2^s), s=0..12 by repeated squaring (double) ----
    {
        double m00 = -ba1, m01 = -ba2, m10 = 1.0, m11 = 0.0;   // M
        for (int s = 0; s < 10; s++) {                          // -> M^1024
            double n00 = m00 * m00 + m01 * m10, n01 = m00 * m01 + m01 * m11;
            double n10 = m10 * m00 + m11 * m10, n11 = m10 * m01 + m11 * m11;
            m00 = n00; m01 = n01; m10 = n10; m11 = n11;
        }
        for (int s = 0; s < 13; s++) {
            g_Ms[s][0] = m00; g_Ms[s][1] = m01; g_Ms[s][2] = m10; g_Ms[s][3] = m11;
            double n00 = m00 * m00 + m01 * m10, n01 = m00 * m01 + m01 * m11;
            double n10 = m10 * m00 + m11 * m10, n11 = m10 * m01 + m11 * m11;
            m00 = n00; m01 = n01; m10 = n10; m11 = n11;
        }
    }

    // ---- envelope ----
    double nD = (double)N_TOT;
    double attack  = 1.0 + (double)envp[0] * 0.1 * nD;
    double release = 1.0 + (double)envp[2] * 0.1 * nD;
    double sustain = fmin(fmax((double)envp[1], 0.0), 1.0);

    g_par[0] = (float)d2;
    g_par[1] = (float)h3;          // feedbackamt
    g_par[2] = (float)bb0; g_par[3] = (float)bb1; g_par[4] = (float)bb2;
    g_par[5] = (float)ba1; g_par[6] = (float)ba2;
    g_par[7] = (float)(1.0 / attack);
    g_par[8] = (float)(1.0 / release);
    g_par[9] = (float)(sustain * h4);
}

// ============================================================
// Karplus chunk runner: NS steps, prefetch depth 4, one barrier
// per step (double-buffered b). Optionally writes outputs.
// ============================================================
template<int NS, bool WRITE>
__device__ __forceinline__ void ks_run(const float* __restrict__ fp,
                                       float* __restrict__ op,
                                       float& a, float (*b)[W],
                                       bool act, int i, int im1,
                                       float d2, float fa) {
    float xr[4];
    #pragma unroll
    for (int q = 0; q < 4; q++)
        xr[q] = (act && q < NS) ? fp[(size_t)q * W] : 0.0f;

    #pragma unroll 4
    for (int s = 0; s < NS; s++) {
        float x = xr[s & 3];
        if (act && (s + 4) < NS) xr[s & 3] = fp[(size_t)(s + 4) * W];
        float u = tanhf(fa * x);
        float t = a + u;
        if (act) b[s & 1][i] = t;
        __syncthreads();
        if (act) {
            a = d2 * (t + b[s & 1][im1]);
            if (WRITE) op[(size_t)s * W] = a;
        }
        __syncthreads();
    }
}

// ============================================================
// Karplus pass 1: zero-init chunk runs -> end states d_c
// ============================================================
__global__ void __launch_bounds__(896) ks_pass1(const float* __restrict__ fb) {
    __shared__ float b[2][W];
    int c = blockIdx.x;
    int i = threadIdx.x;
    bool act = i < W;
    int im1 = (i == 0) ? (W - 1) : (i - 1);
    float d2 = g_par[0], fa = g_par[1];

    float a = 0.0f;
    const float* fp = fb + (size_t)c * MCH * W + i;
    ks_run<MCH, false>(fp, nullptr, a, b, act, i, im1, d2, fa);
    if (act) g_dstate[c * WP + i] = a;
}

// ============================================================
// Karplus combine: 148 sequential boundaries,
// v_c = S^64 * v_{c-1} + d_{c-1}, S^64 truncated to 41 taps.
// 221 active threads x 4 outputs, float4 smem loads, K in regs.
// ============================================================
__global__ void __launch_bounds__(224) ks_combine() {
    __shared__ __align__(16) float ve[W + 64 + 4];   // [0,64): wrap mirror
    int t = threadIdx.x;

    float Kr[NT];
    #pragma unroll
    for (int j = 0; j < NT; j++) Kr[j] = g_K64[J0 + j];

    // init: v = wt; also chunk-0 start state
    for (int p = t; p < W; p += 224) {
        float w = g_wt[p];
        ve[p + 64] = w;
        g_vstart[p] = w;
        if (p >= W - 64) ve[p - (W - 64)] = w;
    }
    __syncthreads();

    int o0 = t * 4;
    bool activ = o0 < W;       // t <= 220
    bool full  = (o0 + 3) < W; // t <= 219

    float4 dv = make_float4(0.f, 0.f, 0.f, 0.f);
    if (activ) dv = *(const float4*)(g_dstate + o0);   // row 0 (for c=1)

    for (int c = 1; c < NCH; c++) {
        float4 dnext = make_float4(0.f, 0.f, 0.f, 0.f);
        if (activ && c < NFULL)
            dnext = *(const float4*)(g_dstate + (size_t)c * WP + o0);

        float a0 = dv.x, a1 = dv.y, a2 = dv.z, a3 = dv.w;
        float w[44];
        if (activ) {
            #pragma unroll
            for (int m = 0; m < 11; m++) {
                float4 q = *(const float4*)&ve[o0 + 12 + 4 * m];
                w[4 * m + 0] = q.x; w[4 * m + 1] = q.y;
                w[4 * m + 2] = q.z; w[4 * m + 3] = q.w;
            }
            #pragma unroll
            for (int jj = 0; jj < NT; jj++) {
                float k = Kr[jj];
                a0 = fmaf(k, w[40 - jj + 0], a0);
                a1 = fmaf(k, w[40 - jj + 1], a1);
                a2 = fmaf(k, w[40 - jj + 2], a2);
                a3 = fmaf(k, w[40 - jj + 3], a3);
            }
        }
        __syncthreads();
        if (activ) {
            float* vs = g_vstart + (size_t)c * WP + o0;
            if (full) {
                ve[o0 + 64] = a0; ve[o0 + 65] = a1; ve[o0 + 66] = a2; ve[o0 + 67] = a3;
                *(float4*)vs = make_float4(a0, a1, a2, a3);
                if (o0 + 0 >= W - 64) ve[o0 + 0 - (W - 64)] = a0;
                if (o0 + 1 >= W - 64) ve[o0 + 1 - (W - 64)] = a1;
                if (o0 + 2 >= W - 64) ve[o0 + 2 - (W - 64)] = a2;
                if (o0 + 3 >= W - 64) ve[o0 + 3 - (W - 64)] = a3;
            } else {
                // edge thread: outputs 880, 881 only
                ve[o0 + 64] = a0; ve[o0 + 65] = a1;
                vs[0] = a0; vs[1] = a1;
                ve[o0 + 0 - (W - 64)] = a0;
                ve[o0 + 1 - (W - 64)] = a1;
            }
        }
        __syncthreads();
        dv = dnext;
    }
}

// ============================================================
// Karplus pass 2: replay chunks from exact start states, write
// outputs; last chunk handles the 788-sample remainder + fade.
// ============================================================
__global__ void __launch_bounds__(896) ks_pass2(const float* __restrict__ fb) {
    __shared__ float b[2][W];
    int c = blockIdx.x;
    int i = threadIdx.x;
    bool act = i < W;
    int im1 = (i == 0) ? (W - 1) : (i - 1);
    float d2 = g_par[0], fa = g_par[1];

    float a = act ? g_vstart[(size_t)c * WP + i] : 0.0f;
    __syncthreads();

    const float* fp = fb   + (size_t)c * MCH * W + i;
    float*       op = g_ks + (size_t)c * MCH * W + i;

    if (c < NCH - 1) {
        ks_run<MCH, true>(fp, op, a, b, act, i, im1, d2, fa);
    } else {
        ks_run<LASTS, true>(fp, op, a, b, act, i, im1, d2, fa);
        // one extra smoothing (no input add), output first REM samples w/ fade
        if (act) b[0][i] = a;
        __syncthreads();
        if (i < REM) {
            float fin = d2 * (b[0][i] + b[0][im1]);
            int g = NB * W + i;
            if (g >= N_TOT - 256) fin *= (float)(N_TOT - 1 - g) * (1.0f / 255.0f);
            g_ks[g] = fin;
        }
    }
}

// ============================================================
// Band-reject pass A: per-chunk zero-init runs -> end states
// ============================================================
__global__ void __launch_bounds__(256) bq_passA() {
    int c = blockIdx.x * blockDim.x + threadIdx.x;
    if (c >= PBQ) return;
    float b0 = g_par[2], b1 = g_par[3], b2 = g_par[4], a1 = g_par[5], a2 = g_par[6];
    int start = c * LBQ;
    float x1 = (c > 0) ? g_ks[start - 1] : 0.0f;
    float x2 = (c > 0) ? g_ks[start - 2] : 0.0f;
    float y1 = 0.0f, y2 = 0.0f;
    const float4* kp = (const float4*)(g_ks + start);
    float4 v = kp[0];
    #pragma unroll 2
    for (int q = 0; q < LBQ / 4; q++) {
        float4 nv = (q + 1 < LBQ / 4) ? kp[q + 1] : make_float4(0.f, 0.f, 0.f, 0.f);
        float xs[4] = {v.x, v.y, v.z, v.w};
        #pragma unroll
        for (int e = 0; e < 4; e++) {
            float xn = xs[e];
            float cn = b0 * xn + b1 * x1 + b2 * x2;
            float yn = cn - a1 * y1 - a2 * y2;
            x2 = x1; x1 = xn; y2 = y1; y1 = yn;
        }
        v = nv;
    }
    g_bqd[2 * c] = y1;
    g_bqd[2 * c + 1] = y2;
}

// ============================================================
// Band-reject scan: 1024 threads, each pre-combines 8 chunks in
// registers, Kogge-Stone over 1024 aggregates, then replay.
// ============================================================
__global__ void __launch_bounds__(1024) bq_scan() {
    __shared__ float2 sv[1024];
    int t = threadIdx.x;
    float A00 = (float)g_Ms[0][0], A01 = (float)g_Ms[0][1];
    float A10 = (float)g_Ms[0][2], A11 = (float)g_Ms[0][3];

    float2 dloc[8];
    #pragma unroll
    for (int e = 0; e < 8; e++) {
        int c = t * 8 + e;
        dloc[e] = make_float2(g_bqd[2 * c], g_bqd[2 * c + 1]);
    }
    // zero-init combine of this thread's 8 chunks
    float vx = 0.f, vy = 0.f;
    #pragma unroll
    for (int e = 0; e < 8; e++) {
        float nx = A00 * vx + A01 * vy + dloc[e].x;
        float ny = A10 * vx + A11 * vy + dloc[e].y;
        vx = nx; vy = ny;
    }
    sv[t] = make_float2(vx, vy);
    __syncthreads();

    // Kogge-Stone inclusive scan over 1024 aggregates
    for (int s = 0; s < 10; s++) {
        int off = 1 << s;
        float B00 = (float)g_Ms[3 + s][0], B01 = (float)g_Ms[3 + s][1];
        float B10 = (float)g_Ms[3 + s][2], B11 = (float)g_Ms[3 + s][3];
        float ax = 0.f, ay = 0.f;
        if (t >= off) {
            float2 src = sv[t - off];
            ax = B00 * src.x + B01 * src.y;
            ay = B10 * src.x + B11 * src.y;
        }
        __syncthreads();
        sv[t].x += ax; sv[t].y += ay;
        __syncthreads();
    }

    // exclusive prefix, replay 8 chunks storing start states
    float ex = 0.f, ey = 0.f;
    if (t > 0) { ex = sv[t - 1].x; ey = sv[t - 1].y; }
    float px = ex, py = ey;
    #pragma unroll
    for (int e = 0; e < 8; e++) {
        int c = t * 8 + e;
        g_bqs[2 * c] = px; g_bqs[2 * c + 1] = py;
        float nx = A00 * px + A01 * py + dloc[e].x;
        float ny = A10 * px + A11 * py + dloc[e].y;
        px = nx; py = ny;
    }
}

// ============================================================
// Band-reject pass B: replay from exact states, fuse envelope
// ============================================================
__global__ void __launch_bounds__(256) bq_passB(float* __restrict__ out) {
    int c = blockIdx.x * blockDim.x + threadIdx.x;
    if (c >= PBQ) return;
    float b0 = g_par[2], b1 = g_par[3], b2 = g_par[4], a1 = g_par[5], a2 = g_par[6];
    float ia = g_par[7], ir = g_par[8], sg = g_par[9];
    int start = c * LBQ;
    float x1 = (c > 0) ? g_ks[start - 1] : 0.0f;
    float x2 = (c > 0) ? g_ks[start - 2] : 0.0f;
    float y1 = g_bqs[2 * c], y2 = g_bqs[2 * c + 1];
    const float4* kp = (const float4*)(g_ks + start);
    float4*       op = (float4*)(out + start);
    float4 v = kp[0];
    #pragma unroll 2
    for (int q = 0; q < LBQ / 4; q++) {
        float4 nv = (q + 1 < LBQ / 4) ? kp[q + 1] : make_float4(0.f, 0.f, 0.f, 0.f);
        float xs[4] = {v.x, v.y, v.z, v.w};
        float ys[4];
        int n0 = start + q * 4;
        #pragma unroll
        for (int e = 0; e < 4; e++) {
            float xn = xs[e];
            float cn = b0 * xn + b1 * x1 + b2 * x2;
            float yn = cn - a1 * y1 - a2 * y2;
            x2 = x1; x1 = xn; y2 = y1; y1 = yn;
            float fn = (float)(n0 + e);
            float e1 = fminf(fn * ia, 1.0f);
            float e2 = fminf(((float)(N_TOT - 1) - fn) * ir, 1.0f);
            ys[e] = yn * e1 * e2 * sg;
        }
        op[q] = make_float4(ys[0], ys[1], ys[2], ys[3]);
        v = nv;
    }
}

// ============================================================
extern "C" void kernel_launch(void* const* d_in, const int* in_sizes, int n_in,
                              void* d_out, int out_size) {
    const float* fb  = (const float*)d_in[0];
    const float* wt  = (const float*)d_in[1];
    const float* h   = (const float*)d_in[2];
    const float* ep  = (const float*)d_in[3];
    const float* lp2 = (const float*)d_in[4];
    float* out = (float*)d_out;

    setup_kernel<<<1, 128>>>(wt, h, ep, lp2);
    ks_pass1<<<NFULL, 896>>>(fb);
    ks_combine<<<1, 224>>>();
    ks_pass2<<<NCH, 896>>>(fb);
    bq_passA<<<PBQ / 256, 256>>>();
    bq_scan<<<1, 1024>>>();
    bq_passB<<<PBQ / 256, 256>>>(out);
}